// round 2
// baseline (speedup 1.0000x reference)
#include <cuda_runtime.h>
#include <cstdint>

// ============================================================
// IVFBook: codes = argmin_k ||c_k||^2 - 2 x.c_k ; out = C[codes]
// B=4096 rows, D=256, K=65536 centroids (read from in_sizes).
// Output buffer is float32: [B*D floats of quantized x][B floats of codes]
// ============================================================

#define BM 128
#define BN 128
#define KC 16
#define LDT 132      // padded smem row stride (floats)
#define D_DIM 256

__device__ unsigned long long g_best[4096];
__device__ float g_csq[65536];

// monotone float->uint encoding (order preserving for all floats)
__device__ __forceinline__ unsigned enc_f32(float f) {
    unsigned u = __float_as_uint(f);
    return (u & 0x80000000u) ? ~u : (u | 0x80000000u);
}

// packed dual fp32 FMA (sm_103a): acc(2xf32) += a(2xf32) * b(2xf32)
#define FMA_X2(acc, a, b) \
    asm("fma.rn.f32x2 %0, %1, %2, %0;" : "+l"(acc) : "l"(a), "l"(b))
// replicate one f32 into both halves of a 64-bit pair
#define PACK2(d, s) \
    asm("mov.b64 %0, {%1, %1};" : "=l"(d) : "f"(s))

// ---------------- csq: ||c_k||^2 ----------------
__global__ void csq_kernel(const float* __restrict__ C) {
    int row = blockIdx.x * 8 + (threadIdx.x >> 5);
    int lane = threadIdx.x & 31;
    const float4* p = (const float4*)(C + (size_t)row * D_DIM);
    float4 v1 = p[lane];
    float4 v2 = p[lane + 32];
    float s = v1.x * v1.x + v1.y * v1.y + v1.z * v1.z + v1.w * v1.w
            + v2.x * v2.x + v2.y * v2.y + v2.z * v2.z + v2.w * v2.w;
    #pragma unroll
    for (int off = 16; off > 0; off >>= 1)
        s += __shfl_xor_sync(0xFFFFFFFFu, s, off);
    if (lane == 0) g_csq[row] = s;
}

// ---------------- init best keys ----------------
__global__ void init_kernel(int B) {
    int i = blockIdx.x * blockDim.x + threadIdx.x;
    if (i < B) g_best[i] = ~0ull;
}

// ---------------- fused SGEMM + argmin ----------------
__global__ void __launch_bounds__(256) gemm_argmin_kernel(
    const float* __restrict__ X, const float* __restrict__ Cc) {
    __shared__ __align__(16) float As[2][KC * LDT];
    __shared__ __align__(16) float Bs[2][KC * LDT];
    __shared__ unsigned long long sbest[BM];

    const int tid = threadIdx.x;
    const int tx = tid & 15;        // N direction (8 cols)
    const int ty = tid >> 4;        // M direction (8 rows)
    const int m0 = blockIdx.y * BM;
    const int n0 = blockIdx.x * BN;

    if (tid < BM) sbest[tid] = ~0ull;

    // global->smem load mapping: 512 float4 per tile, 2 per thread
    const int r0 = tid >> 2;            // rows 0..63
    const int c0 = tid & 3;             // float4 col within KC
    const int r1 = r0 + 64;             // rows 64..127

    const float* Xa = X + (size_t)(m0 + r0) * D_DIM + c0 * 4;
    const float* Xb = X + (size_t)(m0 + r1) * D_DIM + c0 * 4;
    const float* Ca = Cc + (size_t)(n0 + r0) * D_DIM + c0 * 4;
    const float* Cb = Cc + (size_t)(n0 + r1) * D_DIM + c0 * 4;

    float4 ra0 = *(const float4*)(Xa);
    float4 ra1 = *(const float4*)(Xb);
    float4 rb0 = *(const float4*)(Ca);
    float4 rb1 = *(const float4*)(Cb);

    // store stage 0 (transpose to [k][m] / [k][n])
    {
        float* a = As[0]; float* b = Bs[0];
        a[(c0 * 4 + 0) * LDT + r0] = ra0.x; a[(c0 * 4 + 1) * LDT + r0] = ra0.y;
        a[(c0 * 4 + 2) * LDT + r0] = ra0.z; a[(c0 * 4 + 3) * LDT + r0] = ra0.w;
        a[(c0 * 4 + 0) * LDT + r1] = ra1.x; a[(c0 * 4 + 1) * LDT + r1] = ra1.y;
        a[(c0 * 4 + 2) * LDT + r1] = ra1.z; a[(c0 * 4 + 3) * LDT + r1] = ra1.w;
        b[(c0 * 4 + 0) * LDT + r0] = rb0.x; b[(c0 * 4 + 1) * LDT + r0] = rb0.y;
        b[(c0 * 4 + 2) * LDT + r0] = rb0.z; b[(c0 * 4 + 3) * LDT + r0] = rb0.w;
        b[(c0 * 4 + 0) * LDT + r1] = rb1.x; b[(c0 * 4 + 1) * LDT + r1] = rb1.y;
        b[(c0 * 4 + 2) * LDT + r1] = rb1.z; b[(c0 * 4 + 3) * LDT + r1] = rb1.w;
    }
    __syncthreads();

    unsigned long long acc[8][4];
    #pragma unroll
    for (int i = 0; i < 8; i++)
        #pragma unroll
        for (int j = 0; j < 4; j++) acc[i][j] = 0ull;

    const int NT = D_DIM / KC;  // 16 k-tiles
    int cur = 0;
    for (int kt = 0; kt < NT; ++kt) {
        if (kt + 1 < NT) {
            int off = (kt + 1) * KC;
            ra0 = *(const float4*)(Xa + off);
            ra1 = *(const float4*)(Xb + off);
            rb0 = *(const float4*)(Ca + off);
            rb1 = *(const float4*)(Cb + off);
        }
        // compute on stage cur
        #pragma unroll
        for (int k = 0; k < KC; ++k) {
            const float4* A4 = (const float4*)(As[cur] + k * LDT);
            float4 a0 = A4[ty * 2];
            float4 a1 = A4[ty * 2 + 1];
            const unsigned long long* B8 =
                (const unsigned long long*)(Bs[cur] + k * LDT);
            unsigned long long b0 = B8[tx * 4 + 0];
            unsigned long long b1 = B8[tx * 4 + 1];
            unsigned long long b2 = B8[tx * 4 + 2];
            unsigned long long b3 = B8[tx * 4 + 3];
            float av[8] = {a0.x, a0.y, a0.z, a0.w, a1.x, a1.y, a1.z, a1.w};
            #pragma unroll
            for (int i = 0; i < 8; i++) {
                unsigned long long pa;
                PACK2(pa, av[i]);
                FMA_X2(acc[i][0], pa, b0);
                FMA_X2(acc[i][1], pa, b1);
                FMA_X2(acc[i][2], pa, b2);
                FMA_X2(acc[i][3], pa, b3);
            }
        }
        if (kt + 1 < NT) {
            int nxt = cur ^ 1;
            float* a = As[nxt]; float* b = Bs[nxt];
            a[(c0 * 4 + 0) * LDT + r0] = ra0.x; a[(c0 * 4 + 1) * LDT + r0] = ra0.y;
            a[(c0 * 4 + 2) * LDT + r0] = ra0.z; a[(c0 * 4 + 3) * LDT + r0] = ra0.w;
            a[(c0 * 4 + 0) * LDT + r1] = ra1.x; a[(c0 * 4 + 1) * LDT + r1] = ra1.y;
            a[(c0 * 4 + 2) * LDT + r1] = ra1.z; a[(c0 * 4 + 3) * LDT + r1] = ra1.w;
            b[(c0 * 4 + 0) * LDT + r0] = rb0.x; b[(c0 * 4 + 1) * LDT + r0] = rb0.y;
            b[(c0 * 4 + 2) * LDT + r0] = rb0.z; b[(c0 * 4 + 3) * LDT + r0] = rb0.w;
            b[(c0 * 4 + 0) * LDT + r1] = rb1.x; b[(c0 * 4 + 1) * LDT + r1] = rb1.y;
            b[(c0 * 4 + 2) * LDT + r1] = rb1.z; b[(c0 * 4 + 3) * LDT + r1] = rb1.w;
        }
        __syncthreads();
        cur ^= 1;
    }

    // ---- epilogue: dist = csq - 2*dot, fused argmin ----
    float cs[8];
    #pragma unroll
    for (int j = 0; j < 8; j++)
        cs[j] = __ldg(&g_csq[n0 + tx * 8 + j]);

    #pragma unroll
    for (int i = 0; i < 8; i++) {
        unsigned long long bk = ~0ull;
        #pragma unroll
        for (int j = 0; j < 4; j++) {
            float lo = __uint_as_float((unsigned)(acc[i][j] & 0xFFFFFFFFull));
            float hi = __uint_as_float((unsigned)(acc[i][j] >> 32));
            float d0 = cs[2 * j]     - 2.0f * lo;
            float d1 = cs[2 * j + 1] - 2.0f * hi;
            unsigned n_a = (unsigned)(n0 + tx * 8 + 2 * j);
            unsigned long long k0 = ((unsigned long long)enc_f32(d0) << 32) | n_a;
            unsigned long long k1 = ((unsigned long long)enc_f32(d1) << 32) | (n_a + 1);
            unsigned long long kmin = k0 < k1 ? k0 : k1;
            if (kmin < bk) bk = kmin;
        }
        atomicMin(&sbest[ty * 8 + i], bk);
    }
    __syncthreads();
    if (tid < BM) atomicMin(&g_best[m0 + tid], sbest[tid]);
}

// ---------------- gather winners + codes (codes as float32) ----------------
__global__ void gather_kernel(const float* __restrict__ C, float* __restrict__ out,
                              int B) {
    int b = blockIdx.x;
    unsigned long long key = g_best[b];
    unsigned idx = (unsigned)(key & 0xFFFFFFFFull);
    const float* src = C + (size_t)idx * D_DIM;
    out[(size_t)b * D_DIM + threadIdx.x] = src[threadIdx.x];
    if (threadIdx.x == 0) {
        // codes flattened into the same float32 output buffer after xhat
        out[(size_t)B * D_DIM + b] = (float)idx;
    }
}

extern "C" void kernel_launch(void* const* d_in, const int* in_sizes, int n_in,
                              void* d_out, int out_size) {
    // inputs: xhat_BFD [B,1,D] (unused), x_BD [B,D], centroids [K,D]
    const float* x = (const float*)d_in[1];
    const float* cent = (const float*)d_in[2];
    const int B = in_sizes[1] / D_DIM;      // 4096
    const int K = in_sizes[2] / D_DIM;      // 65536
    float* out = (float*)d_out;

    csq_kernel<<<K / 8, 256>>>(cent);
    init_kernel<<<(B + 255) / 256, 256>>>(B);
    dim3 grid(K / BN, B / BM);
    gemm_argmin_kernel<<<grid, 256>>>(x, cent);
    gather_kernel<<<B, D_DIM>>>(cent, out, B);
}

// round 5
// speedup vs baseline: 1.5511x; 1.5511x over previous
#include <cuda_runtime.h>
#include <cuda_fp16.h>
#include <cstdint>

// ============================================================
// IVFBook: dist = ||c||^2 - 2 x.c ; codes = argmin ; out = C[codes]
// B=4096, D=256, K=65536. 3-pass fp16 mma.sync GEMM + fused argmin.
// Output float32: [B*D quantized x][B codes-as-float]
// ============================================================

#define D_DIM 256
#define BMT 128          // CTA M tile
#define BNT 128          // CTA N tile
#define KCH 32           // K chunk
#define NCH 8            // D_DIM / KCH
#define THREADS 512
#define ROWB 80          // padded smem row stride in bytes (5 x 16B, conflict-free)

// smem plane offsets (each plane 128 rows * 80B = 10240B)
#define P_AH 0
#define P_AL 10240
#define P_BH 20480
#define P_BL 30720

__device__ unsigned long long g_best[4096];
__device__ float g_csq[65536];

__device__ __forceinline__ unsigned enc_f32(float f) {
    unsigned u = __float_as_uint(f);
    return (u & 0x80000000u) ? ~u : (u | 0x80000000u);
}
__device__ __forceinline__ uint32_t smem_u32(const void* p) {
    uint32_t a;
    asm("{ .reg .u64 t; cvta.to.shared.u64 t, %1; cvt.u32.u64 %0, t; }"
        : "=r"(a) : "l"(p));
    return a;
}

#define LDSM4(r0, r1, r2, r3, addr) \
    asm volatile("ldmatrix.sync.aligned.m8n8.x4.shared.b16 {%0,%1,%2,%3}, [%4];" \
                 : "=r"(r0), "=r"(r1), "=r"(r2), "=r"(r3) : "r"(addr))

#define MMA_F16(d, a, b0, b1) \
    asm volatile( \
        "mma.sync.aligned.m16n8k16.row.col.f32.f16.f16.f32 " \
        "{%0,%1,%2,%3},{%4,%5,%6,%7},{%8,%9},{%0,%1,%2,%3};" \
        : "+f"((d)[0]), "+f"((d)[1]), "+f"((d)[2]), "+f"((d)[3]) \
        : "r"((a)[0]), "r"((a)[1]), "r"((a)[2]), "r"((a)[3]), \
          "r"(b0), "r"(b1))

// split 8 floats -> hi plane (8 fp16 = uint4) + lo plane (residual)
__device__ __forceinline__ void split8(float4 v0, float4 v1, uint4& hi, uint4& lo) {
    float f[8] = {v0.x, v0.y, v0.z, v0.w, v1.x, v1.y, v1.z, v1.w};
    unsigned hw[4], lw[4];
    #pragma unroll
    for (int i = 0; i < 4; ++i) {
        __half h0 = __float2half_rn(f[2 * i]);
        __half h1 = __float2half_rn(f[2 * i + 1]);
        float l0f = f[2 * i]     - __half2float(h0);
        float l1f = f[2 * i + 1] - __half2float(h1);
        __half l0 = __float2half_rn(l0f);
        __half l1 = __float2half_rn(l1f);
        hw[i] = ((unsigned)__half_as_ushort(h1) << 16) | __half_as_ushort(h0);
        lw[i] = ((unsigned)__half_as_ushort(l1) << 16) | __half_as_ushort(l0);
    }
    hi = make_uint4(hw[0], hw[1], hw[2], hw[3]);
    lo = make_uint4(lw[0], lw[1], lw[2], lw[3]);
}

// ---------------- csq ----------------
__global__ void csq_kernel(const float* __restrict__ C) {
    int row = blockIdx.x * 8 + (threadIdx.x >> 5);
    int lane = threadIdx.x & 31;
    const float4* p = (const float4*)(C + (size_t)row * D_DIM);
    float4 v1 = p[lane];
    float4 v2 = p[lane + 32];
    float s = v1.x * v1.x + v1.y * v1.y + v1.z * v1.z + v1.w * v1.w
            + v2.x * v2.x + v2.y * v2.y + v2.z * v2.z + v2.w * v2.w;
    #pragma unroll
    for (int off = 16; off > 0; off >>= 1)
        s += __shfl_xor_sync(0xFFFFFFFFu, s, off);
    if (lane == 0) g_csq[row] = s;
}

__global__ void init_kernel(int B) {
    int i = blockIdx.x * blockDim.x + threadIdx.x;
    if (i < B) g_best[i] = ~0ull;
}

// ---------------- mma.sync GEMM + fused argmin ----------------
__global__ void __launch_bounds__(THREADS, 1) gemm_argmin_mma(
    const float* __restrict__ X, const float* __restrict__ Cc) {
    __shared__ __align__(16) unsigned char smraw[4 * 10240];
    __shared__ unsigned long long sbest[BMT];

    const int tid = threadIdx.x;
    const int lane = tid & 31;
    const int wid = tid >> 5;
    const int wm = wid >> 2;        // 0..3 : m32 group
    const int wn = wid & 3;         // 0..3 : n32 group
    const int m0 = (blockIdx.x & 31) * BMT;
    const int n0 = (blockIdx.x >> 5) * BNT;

    if (tid < BMT) sbest[tid] = ~0ull;

    const uint32_t sb = smem_u32(smraw);

    // ---- loader mapping: 512 thr, each loads 8 consecutive k of one row ----
    const int lrow = tid >> 2;          // 0..127
    const int lkb = (tid & 3) * 8;      // 0,8,16,24
    const float* xg = X  + (size_t)(m0 + lrow) * D_DIM + lkb;
    const float* cg = Cc + (size_t)(n0 + lrow) * D_DIM + lkb;
    unsigned char* stsA = smraw + lrow * ROWB + lkb * 2;
    unsigned char* stsB = stsA;         // same offset, different plane

    // ---- ldmatrix per-lane addresses ----
    // A: tiles (m0-7,k0-7)(m8-15,k0-7)(m0-7,k8-15)(m8-15,k8-15)
    const uint32_t aRow = (uint32_t)((wm * 32 + (lane & 15)) * ROWB);
    const uint32_t aK   = (lane & 16) ? 16u : 0u;
    // B: tiles (n0-7,k0-7)(n0-7,k8-15)(n8-15,k0-7)(n8-15,k8-15)
    const uint32_t bRow = (uint32_t)((wn * 32 + (lane & 7) + ((lane & 16) >> 1)) * ROWB);
    const uint32_t bK   = (lane & 8) ? 16u : 0u;

    float acc[2][4][4];
    #pragma unroll
    for (int i = 0; i < 2; ++i)
        #pragma unroll
        for (int j = 0; j < 4; ++j)
            #pragma unroll
            for (int c = 0; c < 4; ++c) acc[i][j][c] = 0.0f;

    // prologue: load chunk 0
    float4 x0 = *(const float4*)(xg);
    float4 x1 = *(const float4*)(xg + 4);
    float4 c0 = *(const float4*)(cg);
    float4 c1 = *(const float4*)(cg + 4);

    for (int kc = 0; kc < NCH; ++kc) {
        if (kc) __syncthreads();           // prev compute done -> smem reusable
        uint4 hi, lo;
        split8(x0, x1, hi, lo);
        *(uint4*)(stsA + P_AH) = hi;
        *(uint4*)(stsA + P_AL) = lo;
        split8(c0, c1, hi, lo);
        *(uint4*)(stsB + P_BH) = hi;
        *(uint4*)(stsB + P_BL) = lo;
        __syncthreads();
        if (kc + 1 < NCH) {                 // prefetch next chunk (hidden by mma)
            int off = (kc + 1) * KCH;
            x0 = *(const float4*)(xg + off);
            x1 = *(const float4*)(xg + off + 4);
            c0 = *(const float4*)(cg + off);
            c1 = *(const float4*)(cg + off + 4);
        }
        #pragma unroll
        for (int ks = 0; ks < 2; ++ks) {    // two k16 steps per chunk
            const uint32_t kB = (uint32_t)(ks * 32);
            unsigned ah[2][4], al[2][4], bh[2][4], bl[2][4];
            #pragma unroll
            for (int mt = 0; mt < 2; ++mt) {
                uint32_t a = sb + aRow + (uint32_t)(mt * 16 * ROWB) + kB + aK;
                LDSM4(ah[mt][0], ah[mt][1], ah[mt][2], ah[mt][3], a + P_AH);
                LDSM4(al[mt][0], al[mt][1], al[mt][2], al[mt][3], a + P_AL);
            }
            #pragma unroll
            for (int np = 0; np < 2; ++np) {
                uint32_t b = sb + bRow + (uint32_t)(np * 16 * ROWB) + kB + bK;
                LDSM4(bh[np][0], bh[np][1], bh[np][2], bh[np][3], b + P_BH);
                LDSM4(bl[np][0], bl[np][1], bl[np][2], bl[np][3], b + P_BL);
            }
            #pragma unroll
            for (int mt = 0; mt < 2; ++mt)
                #pragma unroll
                for (int nt = 0; nt < 4; ++nt) {
                    const int np = nt >> 1, r = (nt & 1) * 2;
                    MMA_F16(acc[mt][nt], ah[mt], bh[np][r], bh[np][r + 1]); // hi*hi
                    MMA_F16(acc[mt][nt], ah[mt], bl[np][r], bl[np][r + 1]); // hi*lo
                    MMA_F16(acc[mt][nt], al[mt], bh[np][r], bh[np][r + 1]); // lo*hi
                }
        }
    }

    // ---- epilogue: dist + argmin reduce ----
    #pragma unroll
    for (int mt = 0; mt < 2; ++mt) {
        #pragma unroll
        for (int half = 0; half < 2; ++half) {
            unsigned long long bk = ~0ull;
            #pragma unroll
            for (int nt = 0; nt < 4; ++nt) {
                const int col = n0 + wn * 32 + nt * 8 + (lane & 3) * 2;
                float2 cs = __ldg((const float2*)(g_csq + col));
                float d0 = fmaf(-2.0f, acc[mt][nt][half * 2 + 0], cs.x);
                float d1 = fmaf(-2.0f, acc[mt][nt][half * 2 + 1], cs.y);
                unsigned long long k0 =
                    ((unsigned long long)enc_f32(d0) << 32) | (unsigned)col;
                unsigned long long k1 =
                    ((unsigned long long)enc_f32(d1) << 32) | (unsigned)(col + 1);
                unsigned long long km = k0 < k1 ? k0 : k1;
                bk = km < bk ? km : bk;
            }
            unsigned long long o;
            o = __shfl_xor_sync(0xFFFFFFFFu, bk, 1); bk = o < bk ? o : bk;
            o = __shfl_xor_sync(0xFFFFFFFFu, bk, 2); bk = o < bk ? o : bk;
            if ((lane & 3) == 0)
                atomicMin(&sbest[wm * 32 + mt * 16 + half * 8 + (lane >> 2)], bk);
        }
    }
    __syncthreads();
    if (tid < BMT) atomicMin(&g_best[m0 + tid], sbest[tid]);
}

// ---------------- gather winners + codes ----------------
__global__ void gather_kernel(const float* __restrict__ C, float* __restrict__ out,
                              int B) {
    int b = blockIdx.x;
    unsigned long long key = g_best[b];
    unsigned idx = (unsigned)(key & 0xFFFFFFFFull);
    const float* src = C + (size_t)idx * D_DIM;
    out[(size_t)b * D_DIM + threadIdx.x] = src[threadIdx.x];
    if (threadIdx.x == 0)
        out[(size_t)B * D_DIM + b] = (float)idx;
}

extern "C" void kernel_launch(void* const* d_in, const int* in_sizes, int n_in,
                              void* d_out, int out_size) {
    const float* x = (const float*)d_in[1];
    const float* cent = (const float*)d_in[2];
    const int B = in_sizes[1] / D_DIM;      // 4096
    const int K = in_sizes[2] / D_DIM;      // 65536
    float* out = (float*)d_out;

    csq_kernel<<<K / 8, 256>>>(cent);
    init_kernel<<<(B + 255) / 256, 256>>>(B);
    const int grid = (B / BMT) * (K / BNT);  // 32 * 512 = 16384
    gemm_argmin_mma<<<grid, THREADS>>>(x, cent);
    gather_kernel<<<B, D_DIM>>>(cent, out, B);
}

// round 6
// speedup vs baseline: 2.1980x; 1.4171x over previous
#include <cuda_runtime.h>
#include <cuda_fp16.h>
#include <cstdint>

// ============================================================
// IVFBook: dist = ||c||^2 - 2 x.c ; codes = argmin ; out = C[codes]
// B=4096, D=256, K=65536.
// Pre-split fp32 -> fp16 hi/lo planes, then 3-pass fp16 mma.sync
// GEMM (cp.async double-buffered) + fused argmin.
// Output float32: [B*D quantized x][B codes-as-float]
// ============================================================

#define D_DIM 256
#define BMT 128          // CTA M tile
#define BNT 128          // CTA N tile
#define KCH 32           // K chunk
#define NCH 8            // D_DIM / KCH
#define THREADS 512
#define ROWB 80          // padded smem row stride (bytes), conflict-free ldmatrix

// smem plane offsets within one stage (each plane 128*80 = 10240B)
#define P_AH 0
#define P_AL 10240
#define P_BH 20480
#define P_BL 30720
#define STAGE_SZ 40960
#define SMEM_DYN (2 * STAGE_SZ)   // 81920

__device__ unsigned long long g_best[4096];
__device__ float g_csq[65536];
__device__ __half g_c_hi[65536 * 256];
__device__ __half g_c_lo[65536 * 256];
__device__ __half g_x_hi[4096 * 256];
__device__ __half g_x_lo[4096 * 256];

__device__ __forceinline__ unsigned enc_f32(float f) {
    unsigned u = __float_as_uint(f);
    return (u & 0x80000000u) ? ~u : (u | 0x80000000u);
}
__device__ __forceinline__ uint32_t smem_u32(const void* p) {
    uint32_t a;
    asm("{ .reg .u64 t; cvta.to.shared.u64 t, %1; cvt.u32.u64 %0, t; }"
        : "=r"(a) : "l"(p));
    return a;
}

#define LDSM4(r0, r1, r2, r3, addr) \
    asm volatile("ldmatrix.sync.aligned.m8n8.x4.shared.b16 {%0,%1,%2,%3}, [%4];" \
                 : "=r"(r0), "=r"(r1), "=r"(r2), "=r"(r3) : "r"(addr))

#define MMA_F16(d, a, b0, b1) \
    asm volatile( \
        "mma.sync.aligned.m16n8k16.row.col.f32.f16.f16.f32 " \
        "{%0,%1,%2,%3},{%4,%5,%6,%7},{%8,%9},{%0,%1,%2,%3};" \
        : "+f"((d)[0]), "+f"((d)[1]), "+f"((d)[2]), "+f"((d)[3]) \
        : "r"((a)[0]), "r"((a)[1]), "r"((a)[2]), "r"((a)[3]), \
          "r"(b0), "r"(b1))

#define CP16(dst, src) \
    asm volatile("cp.async.cg.shared.global [%0], [%1], 16;" \
                 :: "r"(dst), "l"(src) : "memory")
#define CP_COMMIT() asm volatile("cp.async.commit_group;" ::: "memory")
#define CP_WAIT0()  asm volatile("cp.async.wait_group 0;" ::: "memory")

// split 8 floats -> hi (8 fp16 = uint4) + lo residual plane
__device__ __forceinline__ void split8(float4 v0, float4 v1, uint4& hi, uint4& lo) {
    float f[8] = {v0.x, v0.y, v0.z, v0.w, v1.x, v1.y, v1.z, v1.w};
    unsigned hw[4], lw[4];
    #pragma unroll
    for (int i = 0; i < 4; ++i) {
        __half h0 = __float2half_rn(f[2 * i]);
        __half h1 = __float2half_rn(f[2 * i + 1]);
        __half l0 = __float2half_rn(f[2 * i]     - __half2float(h0));
        __half l1 = __float2half_rn(f[2 * i + 1] - __half2float(h1));
        hw[i] = ((unsigned)__half_as_ushort(h1) << 16) | __half_as_ushort(h0);
        lw[i] = ((unsigned)__half_as_ushort(l1) << 16) | __half_as_ushort(l0);
    }
    hi = make_uint4(hw[0], hw[1], hw[2], hw[3]);
    lo = make_uint4(lw[0], lw[1], lw[2], lw[3]);
}

// ---------------- split centroids + csq ----------------
__global__ void split_c_kernel(const float* __restrict__ C) {
    int row = blockIdx.x * 8 + (threadIdx.x >> 5);
    int lane = threadIdx.x & 31;
    const float4* p = (const float4*)(C + (size_t)row * D_DIM + lane * 8);
    float4 v0 = p[0], v1 = p[1];
    uint4 hi, lo;
    split8(v0, v1, hi, lo);
    *(uint4*)(g_c_hi + (size_t)row * D_DIM + lane * 8) = hi;
    *(uint4*)(g_c_lo + (size_t)row * D_DIM + lane * 8) = lo;
    float s = v0.x * v0.x + v0.y * v0.y + v0.z * v0.z + v0.w * v0.w
            + v1.x * v1.x + v1.y * v1.y + v1.z * v1.z + v1.w * v1.w;
    #pragma unroll
    for (int off = 16; off > 0; off >>= 1)
        s += __shfl_xor_sync(0xFFFFFFFFu, s, off);
    if (lane == 0) g_csq[row] = s;
}

// ---------------- split x + init g_best ----------------
__global__ void split_x_kernel(const float* __restrict__ X) {
    int row = blockIdx.x * 8 + (threadIdx.x >> 5);
    int lane = threadIdx.x & 31;
    const float4* p = (const float4*)(X + (size_t)row * D_DIM + lane * 8);
    float4 v0 = p[0], v1 = p[1];
    uint4 hi, lo;
    split8(v0, v1, hi, lo);
    *(uint4*)(g_x_hi + (size_t)row * D_DIM + lane * 8) = hi;
    *(uint4*)(g_x_lo + (size_t)row * D_DIM + lane * 8) = lo;
    if (lane == 0) g_best[row] = ~0ull;
}

// ---------------- mma.sync GEMM + fused argmin ----------------
__global__ void __launch_bounds__(THREADS, 1) gemm_argmin_mma(int dummy) {
    extern __shared__ __align__(16) unsigned char smraw[];
    __shared__ unsigned long long sbest[BMT];

    const int tid = threadIdx.x;
    const int lane = tid & 31;
    const int wid = tid >> 5;
    const int wm = wid >> 2;        // 0..3 : m32 group
    const int wn = wid & 3;         // 0..3 : n32 group
    const int m0 = (blockIdx.x & 31) * BMT;
    const int n0 = (blockIdx.x >> 5) * BNT;

    if (tid < BMT) sbest[tid] = ~0ull;

    const uint32_t sb = smem_u32(smraw);

    // ---- cp.async mapping: row = tid>>2 (0..127), seg = tid&3 (16B) ----
    const int lrow = tid >> 2;
    const int lseg = tid & 3;
    const __half* sAH = g_x_hi + (size_t)(m0 + lrow) * D_DIM + lseg * 8;
    const __half* sAL = g_x_lo + (size_t)(m0 + lrow) * D_DIM + lseg * 8;
    const __half* sBH = g_c_hi + (size_t)(n0 + lrow) * D_DIM + lseg * 8;
    const __half* sBL = g_c_lo + (size_t)(n0 + lrow) * D_DIM + lseg * 8;
    const uint32_t dRow = sb + (uint32_t)(lrow * ROWB + lseg * 16);

    // ---- ldmatrix per-lane addresses (same mapping as validated r5) ----
    const uint32_t aRow = (uint32_t)((wm * 32 + (lane & 15)) * ROWB);
    const uint32_t aK   = (lane & 16) ? 16u : 0u;
    const uint32_t bRow = (uint32_t)((wn * 32 + (lane & 7) + ((lane & 16) >> 1)) * ROWB);
    const uint32_t bK   = (lane & 8) ? 16u : 0u;

    float acc[2][4][4];
    #pragma unroll
    for (int i = 0; i < 2; ++i)
        #pragma unroll
        for (int j = 0; j < 4; ++j)
            #pragma unroll
            for (int c = 0; c < 4; ++c) acc[i][j][c] = 0.0f;

    // prologue: issue chunk 0 into stage 0
    {
        const uint32_t d = dRow;
        CP16(d + P_AH, sAH); CP16(d + P_AL, sAL);
        CP16(d + P_BH, sBH); CP16(d + P_BL, sBL);
        CP_COMMIT();
    }

    for (int kc = 0; kc < NCH; ++kc) {
        CP_WAIT0();
        __syncthreads();            // chunk kc visible; compute kc-1 done everywhere
        if (kc + 1 < NCH) {         // stream chunk kc+1 into the other stage
            const int off = (kc + 1) * KCH;
            const uint32_t d = dRow + (uint32_t)(((kc + 1) & 1) * STAGE_SZ);
            CP16(d + P_AH, sAH + off); CP16(d + P_AL, sAL + off);
            CP16(d + P_BH, sBH + off); CP16(d + P_BL, sBL + off);
            CP_COMMIT();
        }
        const uint32_t stg = sb + (uint32_t)((kc & 1) * STAGE_SZ);
        #pragma unroll
        for (int ks = 0; ks < 2; ++ks) {    // two k16 steps per chunk
            const uint32_t kB = (uint32_t)(ks * 32);
            unsigned ah[2][4], al[2][4], bh[2][4], bl[2][4];
            #pragma unroll
            for (int mt = 0; mt < 2; ++mt) {
                uint32_t a = stg + aRow + (uint32_t)(mt * 16 * ROWB) + kB + aK;
                LDSM4(ah[mt][0], ah[mt][1], ah[mt][2], ah[mt][3], a + P_AH);
                LDSM4(al[mt][0], al[mt][1], al[mt][2], al[mt][3], a + P_AL);
            }
            #pragma unroll
            for (int np = 0; np < 2; ++np) {
                uint32_t b = stg + bRow + (uint32_t)(np * 16 * ROWB) + kB + bK;
                LDSM4(bh[np][0], bh[np][1], bh[np][2], bh[np][3], b + P_BH);
                LDSM4(bl[np][0], bl[np][1], bl[np][2], bl[np][3], b + P_BL);
            }
            #pragma unroll
            for (int mt = 0; mt < 2; ++mt)
                #pragma unroll
                for (int nt = 0; nt < 4; ++nt) {
                    const int np = nt >> 1, r = (nt & 1) * 2;
                    MMA_F16(acc[mt][nt], ah[mt], bh[np][r], bh[np][r + 1]); // hi*hi
                    MMA_F16(acc[mt][nt], ah[mt], bl[np][r], bl[np][r + 1]); // hi*lo
                    MMA_F16(acc[mt][nt], al[mt], bh[np][r], bh[np][r + 1]); // lo*hi
                }
        }
    }

    // ---- epilogue: dist + argmin reduce ----
    #pragma unroll
    for (int mt = 0; mt < 2; ++mt) {
        #pragma unroll
        for (int half = 0; half < 2; ++half) {
            unsigned long long bk = ~0ull;
            #pragma unroll
            for (int nt = 0; nt < 4; ++nt) {
                const int col = n0 + wn * 32 + nt * 8 + (lane & 3) * 2;
                float2 cs = __ldg((const float2*)(g_csq + col));
                float d0 = fmaf(-2.0f, acc[mt][nt][half * 2 + 0], cs.x);
                float d1 = fmaf(-2.0f, acc[mt][nt][half * 2 + 1], cs.y);
                unsigned long long k0 =
                    ((unsigned long long)enc_f32(d0) << 32) | (unsigned)col;
                unsigned long long k1 =
                    ((unsigned long long)enc_f32(d1) << 32) | (unsigned)(col + 1);
                unsigned long long km = k0 < k1 ? k0 : k1;
                bk = km < bk ? km : bk;
            }
            unsigned long long o;
            o = __shfl_xor_sync(0xFFFFFFFFu, bk, 1); bk = o < bk ? o : bk;
            o = __shfl_xor_sync(0xFFFFFFFFu, bk, 2); bk = o < bk ? o : bk;
            if ((lane & 3) == 0)
                atomicMin(&sbest[wm * 32 + mt * 16 + half * 8 + (lane >> 2)], bk);
        }
    }
    __syncthreads();
    if (tid < BMT) atomicMin(&g_best[m0 + tid], sbest[tid]);
}

// ---------------- gather winners + codes ----------------
__global__ void gather_kernel(const float* __restrict__ C, float* __restrict__ out,
                              int B) {
    int b = blockIdx.x;
    unsigned long long key = g_best[b];
    unsigned idx = (unsigned)(key & 0xFFFFFFFFull);
    const float* src = C + (size_t)idx * D_DIM;
    out[(size_t)b * D_DIM + threadIdx.x] = src[threadIdx.x];
    if (threadIdx.x == 0)
        out[(size_t)B * D_DIM + b] = (float)idx;
}

extern "C" void kernel_launch(void* const* d_in, const int* in_sizes, int n_in,
                              void* d_out, int out_size) {
    const float* x = (const float*)d_in[1];
    const float* cent = (const float*)d_in[2];
    const int B = in_sizes[1] / D_DIM;      // 4096
    const int K = in_sizes[2] / D_DIM;      // 65536
    float* out = (float*)d_out;

    static int smem_set = 0;
    if (!smem_set) {
        cudaFuncSetAttribute(gemm_argmin_mma,
                             cudaFuncAttributeMaxDynamicSharedMemorySize, SMEM_DYN);
        smem_set = 1;
    }

    split_c_kernel<<<K / 8, 256>>>(cent);
    split_x_kernel<<<B / 8, 256>>>(x);
    const int grid = (B / BMT) * (K / BNT);  // 16384
    gemm_argmin_mma<<<grid, THREADS, SMEM_DYN>>>(0);
    gather_kernel<<<B, D_DIM>>>(cent, out, B);
}

// round 7
// speedup vs baseline: 3.1596x; 1.4375x over previous
#include <cuda_runtime.h>
#include <cuda_fp16.h>
#include <cstdint>

// ============================================================
// IVFBook: dist = ||c||^2 - 2 x.c ; codes = argmin ; out = C[codes]
// B=4096, D=256, K=65536.
// Phase 1: 1-pass fp16 mma.sync approx GEMM, per-(row,ntile) min keys.
// Phase 2: per-row rerank of tiles within margin of global approx min,
//          exact fp32 distances decide the winner (provably safe).
// Output float32: [B*D quantized x][B codes-as-float]
// ============================================================

#define D_DIM 256
#define BMT 128          // CTA M tile
#define BNT 128          // CTA N tile
#define KCH 32           // K chunk
#define NCH 8            // D_DIM / KCH
#define THREADS 512
#define ROWB 80          // padded smem row stride (bytes), conflict-free ldmatrix
#define NT_TILES 512     // K / BNT
#define M_MARGIN 0.75f   // >= 2*eps hard bound on approx-dist error

// smem plane offsets within one stage (each plane 128*80 = 10240B)
#define P_AH 0
#define P_BH 10240
#define STAGE_SZ 20480

__device__ unsigned long long g_best[4096];
__device__ unsigned long long g_lmin[4096 * NT_TILES];   // 16MB
__device__ float g_csq[65536];
__device__ __half g_c_hi[65536 * 256];
__device__ __half g_x_hi[4096 * 256];

__device__ __forceinline__ unsigned enc_f32(float f) {
    unsigned u = __float_as_uint(f);
    return (u & 0x80000000u) ? ~u : (u | 0x80000000u);
}
__device__ __forceinline__ float dec_f32(unsigned u) {
    unsigned v = (u & 0x80000000u) ? (u & 0x7FFFFFFFu) : ~u;
    return __uint_as_float(v);
}
__device__ __forceinline__ uint32_t smem_u32(const void* p) {
    uint32_t a;
    asm("{ .reg .u64 t; cvta.to.shared.u64 t, %1; cvt.u32.u64 %0, t; }"
        : "=r"(a) : "l"(p));
    return a;
}

#define LDSM4(r0, r1, r2, r3, addr) \
    asm volatile("ldmatrix.sync.aligned.m8n8.x4.shared.b16 {%0,%1,%2,%3}, [%4];" \
                 : "=r"(r0), "=r"(r1), "=r"(r2), "=r"(r3) : "r"(addr))

#define MMA_F16(d, a, b0, b1) \
    asm volatile( \
        "mma.sync.aligned.m16n8k16.row.col.f32.f16.f16.f32 " \
        "{%0,%1,%2,%3},{%4,%5,%6,%7},{%8,%9},{%0,%1,%2,%3};" \
        : "+f"((d)[0]), "+f"((d)[1]), "+f"((d)[2]), "+f"((d)[3]) \
        : "r"((a)[0]), "r"((a)[1]), "r"((a)[2]), "r"((a)[3]), \
          "r"(b0), "r"(b1))

#define CP16(dst, src) \
    asm volatile("cp.async.cg.shared.global [%0], [%1], 16;" \
                 :: "r"(dst), "l"(src) : "memory")
#define CP_COMMIT() asm volatile("cp.async.commit_group;" ::: "memory")
#define CP_WAIT0()  asm volatile("cp.async.wait_group 0;" ::: "memory")

// 8 floats -> 8 fp16 (hi plane)
__device__ __forceinline__ uint4 pack8(float4 v0, float4 v1) {
    float f[8] = {v0.x, v0.y, v0.z, v0.w, v1.x, v1.y, v1.z, v1.w};
    unsigned hw[4];
    #pragma unroll
    for (int i = 0; i < 4; ++i) {
        __half h0 = __float2half_rn(f[2 * i]);
        __half h1 = __float2half_rn(f[2 * i + 1]);
        hw[i] = ((unsigned)__half_as_ushort(h1) << 16) | __half_as_ushort(h0);
    }
    return make_uint4(hw[0], hw[1], hw[2], hw[3]);
}

// ---------------- split centroids (hi plane) + csq ----------------
__global__ void split_c_kernel(const float* __restrict__ C) {
    int row = blockIdx.x * 8 + (threadIdx.x >> 5);
    int lane = threadIdx.x & 31;
    const float4* p = (const float4*)(C + (size_t)row * D_DIM + lane * 8);
    float4 v0 = p[0], v1 = p[1];
    *(uint4*)(g_c_hi + (size_t)row * D_DIM + lane * 8) = pack8(v0, v1);
    float s = v0.x * v0.x + v0.y * v0.y + v0.z * v0.z + v0.w * v0.w
            + v1.x * v1.x + v1.y * v1.y + v1.z * v1.z + v1.w * v1.w;
    #pragma unroll
    for (int off = 16; off > 0; off >>= 1)
        s += __shfl_xor_sync(0xFFFFFFFFu, s, off);
    if (lane == 0) g_csq[row] = s;
}

// ---------------- split x (hi plane) ----------------
__global__ void split_x_kernel(const float* __restrict__ X) {
    int row = blockIdx.x * 8 + (threadIdx.x >> 5);
    int lane = threadIdx.x & 31;
    const float4* p = (const float4*)(X + (size_t)row * D_DIM + lane * 8);
    *(uint4*)(g_x_hi + (size_t)row * D_DIM + lane * 8) = pack8(p[0], p[1]);
}

// ---------------- Phase 1: 1-pass approx GEMM + per-tile min ----------------
__global__ void __launch_bounds__(THREADS, 1) gemm_approx_mma(int dummy) {
    __shared__ __align__(16) unsigned char smraw[2 * STAGE_SZ];
    __shared__ unsigned long long sbest[BMT];

    const int tid = threadIdx.x;
    const int lane = tid & 31;
    const int wid = tid >> 5;
    const int wm = wid >> 2;        // 0..3 : m32 group
    const int wn = wid & 3;         // 0..3 : n32 group
    const int mt_idx = blockIdx.x & 31;
    const int nt_idx = blockIdx.x >> 5;
    const int m0 = mt_idx * BMT;
    const int n0 = nt_idx * BNT;

    if (tid < BMT) sbest[tid] = ~0ull;

    const uint32_t sb = smem_u32(smraw);

    // ---- cp.async mapping: row = tid>>2 (0..127), seg = tid&3 (16B) ----
    const int lrow = tid >> 2;
    const int lseg = tid & 3;
    const __half* sAH = g_x_hi + (size_t)(m0 + lrow) * D_DIM + lseg * 8;
    const __half* sBH = g_c_hi + (size_t)(n0 + lrow) * D_DIM + lseg * 8;
    const uint32_t dRow = sb + (uint32_t)(lrow * ROWB + lseg * 16);

    // ---- ldmatrix per-lane addresses (validated mapping) ----
    const uint32_t aRow = (uint32_t)((wm * 32 + (lane & 15)) * ROWB);
    const uint32_t aK   = (lane & 16) ? 16u : 0u;
    const uint32_t bRow = (uint32_t)((wn * 32 + (lane & 7) + ((lane & 16) >> 1)) * ROWB);
    const uint32_t bK   = (lane & 8) ? 16u : 0u;

    float acc[2][4][4];
    #pragma unroll
    for (int i = 0; i < 2; ++i)
        #pragma unroll
        for (int j = 0; j < 4; ++j)
            #pragma unroll
            for (int c = 0; c < 4; ++c) acc[i][j][c] = 0.0f;

    // prologue: chunk 0 -> stage 0
    CP16(dRow + P_AH, sAH);
    CP16(dRow + P_BH, sBH);
    CP_COMMIT();

    for (int kc = 0; kc < NCH; ++kc) {
        CP_WAIT0();
        __syncthreads();
        if (kc + 1 < NCH) {
            const int off = (kc + 1) * KCH;
            const uint32_t d = dRow + (uint32_t)(((kc + 1) & 1) * STAGE_SZ);
            CP16(d + P_AH, sAH + off);
            CP16(d + P_BH, sBH + off);
            CP_COMMIT();
        }
        const uint32_t stg = sb + (uint32_t)((kc & 1) * STAGE_SZ);
        #pragma unroll
        for (int ks = 0; ks < 2; ++ks) {
            const uint32_t kB = (uint32_t)(ks * 32);
            unsigned ah[2][4], bh[2][4];
            #pragma unroll
            for (int mt = 0; mt < 2; ++mt) {
                uint32_t a = stg + aRow + (uint32_t)(mt * 16 * ROWB) + kB + aK;
                LDSM4(ah[mt][0], ah[mt][1], ah[mt][2], ah[mt][3], a + P_AH);
            }
            #pragma unroll
            for (int np = 0; np < 2; ++np) {
                uint32_t b = stg + bRow + (uint32_t)(np * 16 * ROWB) + kB + bK;
                LDSM4(bh[np][0], bh[np][1], bh[np][2], bh[np][3], b + P_BH);
            }
            #pragma unroll
            for (int mt = 0; mt < 2; ++mt)
                #pragma unroll
                for (int nt = 0; nt < 4; ++nt) {
                    const int np = nt >> 1, r = (nt & 1) * 2;
                    MMA_F16(acc[mt][nt], ah[mt], bh[np][r], bh[np][r + 1]);
                }
        }
    }

    // ---- epilogue: approx dist + per-row CTA min ----
    #pragma unroll
    for (int mt = 0; mt < 2; ++mt) {
        #pragma unroll
        for (int half = 0; half < 2; ++half) {
            unsigned long long bk = ~0ull;
            #pragma unroll
            for (int nt = 0; nt < 4; ++nt) {
                const int col = n0 + wn * 32 + nt * 8 + (lane & 3) * 2;
                float2 cs = __ldg((const float2*)(g_csq + col));
                float d0 = fmaf(-2.0f, acc[mt][nt][half * 2 + 0], cs.x);
                float d1 = fmaf(-2.0f, acc[mt][nt][half * 2 + 1], cs.y);
                unsigned long long k0 =
                    ((unsigned long long)enc_f32(d0) << 32) | (unsigned)col;
                unsigned long long k1 =
                    ((unsigned long long)enc_f32(d1) << 32) | (unsigned)(col + 1);
                unsigned long long km = k0 < k1 ? k0 : k1;
                bk = km < bk ? km : bk;
            }
            unsigned long long o;
            o = __shfl_xor_sync(0xFFFFFFFFu, bk, 1); bk = o < bk ? o : bk;
            o = __shfl_xor_sync(0xFFFFFFFFu, bk, 2); bk = o < bk ? o : bk;
            if ((lane & 3) == 0)
                atomicMin(&sbest[wm * 32 + mt * 16 + half * 8 + (lane >> 2)], bk);
        }
    }
    __syncthreads();
    if (tid < BMT)
        g_lmin[(size_t)(m0 + tid) * NT_TILES + nt_idx] = sbest[tid];
}

// ---------------- Phase 2: per-row exact rerank ----------------
__global__ void __launch_bounds__(128) rerank_kernel(
    const float* __restrict__ X, const float* __restrict__ Cc) {
    __shared__ float xs[D_DIM];
    __shared__ unsigned long long skeys[NT_TILES];
    __shared__ unsigned long long swarp[4];

    const int row = blockIdx.x;
    const int tid = threadIdx.x;
    const int lane = tid & 31;
    const int wid = tid >> 5;

    // load keys + x row, find global approx min
    const unsigned long long* lm = g_lmin + (size_t)row * NT_TILES;
    unsigned long long mn = ~0ull;
    #pragma unroll
    for (int i = 0; i < NT_TILES / 128; ++i) {
        unsigned long long v = lm[tid + i * 128];
        skeys[tid + i * 128] = v;
        mn = v < mn ? v : mn;
    }
    xs[tid] = X[(size_t)row * D_DIM + tid];
    xs[tid + 128] = X[(size_t)row * D_DIM + 128 + tid];
    #pragma unroll
    for (int off = 16; off > 0; off >>= 1) {
        unsigned long long o = __shfl_xor_sync(0xFFFFFFFFu, mn, off);
        mn = o < mn ? o : mn;
    }
    if (lane == 0) swarp[wid] = mn;
    __syncthreads();
    mn = swarp[0];
    #pragma unroll
    for (int w = 1; w < 4; ++w) mn = swarp[w] < mn ? swarp[w] : mn;

    const float thr = dec_f32((unsigned)(mn >> 32)) + M_MARGIN;
    const unsigned thr_enc = enc_f32(thr);

    unsigned long long best = ~0ull;
    for (int t = 0; t < NT_TILES; ++t) {
        if ((unsigned)(skeys[t] >> 32) <= thr_enc) {
            // exact fp32 rerank of all 128 cols in this tile; warp wid
            // handles 32 of them.
            const int base = t * BNT + wid * 32;
            for (int c = 0; c < 32; ++c) {
                const int col = base + c;
                const float4* cp = (const float4*)(Cc + (size_t)col * D_DIM + lane * 8);
                float4 c0 = cp[0], c1 = cp[1];
                const float* xp = xs + lane * 8;
                float s = c0.x * xp[0];
                s = fmaf(c0.y, xp[1], s);
                s = fmaf(c0.z, xp[2], s);
                s = fmaf(c0.w, xp[3], s);
                s = fmaf(c1.x, xp[4], s);
                s = fmaf(c1.y, xp[5], s);
                s = fmaf(c1.z, xp[6], s);
                s = fmaf(c1.w, xp[7], s);
                #pragma unroll
                for (int off = 16; off > 0; off >>= 1)
                    s += __shfl_xor_sync(0xFFFFFFFFu, s, off);
                float dist = fmaf(-2.0f, s, g_csq[col]);
                unsigned long long key =
                    ((unsigned long long)enc_f32(dist) << 32) | (unsigned)col;
                best = key < best ? key : best;
            }
        }
    }
    // block-reduce exact best (uniform within warp already)
    if (lane == 0) swarp[wid] = best;
    __syncthreads();
    if (tid == 0) {
        unsigned long long b = swarp[0];
        #pragma unroll
        for (int w = 1; w < 4; ++w) b = swarp[w] < b ? swarp[w] : b;
        g_best[row] = b;
    }
}

// ---------------- gather winners + codes ----------------
__global__ void gather_kernel(const float* __restrict__ C, float* __restrict__ out,
                              int B) {
    int b = blockIdx.x;
    unsigned long long key = g_best[b];
    unsigned idx = (unsigned)(key & 0xFFFFFFFFull);
    const float* src = C + (size_t)idx * D_DIM;
    out[(size_t)b * D_DIM + threadIdx.x] = src[threadIdx.x];
    if (threadIdx.x == 0)
        out[(size_t)B * D_DIM + b] = (float)idx;
}

extern "C" void kernel_launch(void* const* d_in, const int* in_sizes, int n_in,
                              void* d_out, int out_size) {
    const float* x = (const float*)d_in[1];
    const float* cent = (const float*)d_in[2];
    const int B = in_sizes[1] / D_DIM;      // 4096
    const int K = in_sizes[2] / D_DIM;      // 65536
    float* out = (float*)d_out;

    split_c_kernel<<<K / 8, 256>>>(cent);
    split_x_kernel<<<B / 8, 256>>>(x);
    const int grid = (B / BMT) * (K / BNT);  // 16384
    gemm_approx_mma<<<grid, THREADS>>>(0);
    rerank_kernel<<<B, 128>>>(x, cent);
    gather_kernel<<<B, D_DIM>>>(cent, out, B);
}

// round 8
// speedup vs baseline: 3.5200x; 1.1141x over previous
#include <cuda_runtime.h>
#include <cuda_fp16.h>
#include <cstdint>

// ============================================================
// IVFBook: dist = ||c||^2 - 2 x.c ; codes = argmin ; out = C[codes]
// B=4096, D=256, K=65536.
// Phase 1: 1-pass fp16 mma.sync approx GEMM (A-resident smem,
//          B-only 4-stage cp.async pipeline, 16 n-tiles per CTA),
//          per-(row,ntile) min keys.
// Phase 2: per-row exact fp32 rerank of tiles within margin of the
//          global approx min (provably safe bound).
// Output float32: [B*D quantized x][B codes-as-float]
// ============================================================

#define D_DIM 256
#define BMT 128          // CTA M tile
#define BNT 128          // N tile
#define KCH 32           // K chunk (fp16 elems)
#define NCH 8            // D_DIM / KCH
#define THREADS 512
#define ROWB 80          // B smem row stride (bytes)
#define ROWA 528         // A smem row stride (bytes), conflict-free
#define NT_TILES 512     // K / BNT
#define NGT 16           // n-tiles per CTA
#define TOTCH (NGT * NCH)  // 128 chunks per CTA
#define M_MARGIN 0.75f

#define A_BYTES (128 * ROWA)      // 67584
#define B_STAGE (128 * ROWB)      // 10240
#define NSTAGE 4
#define SMEM_DYN (A_BYTES + NSTAGE * B_STAGE)   // 108544

__device__ unsigned long long g_best[4096];
__device__ unsigned long long g_lmin[4096 * NT_TILES];   // 16MB
__device__ float g_csq[65536];
__device__ __half g_c_hi[65536 * 256];
__device__ __half g_x_hi[4096 * 256];

__device__ __forceinline__ unsigned enc_f32(float f) {
    unsigned u = __float_as_uint(f);
    return (u & 0x80000000u) ? ~u : (u | 0x80000000u);
}
__device__ __forceinline__ float dec_f32(unsigned u) {
    unsigned v = (u & 0x80000000u) ? (u & 0x7FFFFFFFu) : ~u;
    return __uint_as_float(v);
}
__device__ __forceinline__ uint32_t smem_u32(const void* p) {
    uint32_t a;
    asm("{ .reg .u64 t; cvta.to.shared.u64 t, %1; cvt.u32.u64 %0, t; }"
        : "=r"(a) : "l"(p));
    return a;
}

#define LDSM4(r0, r1, r2, r3, addr) \
    asm volatile("ldmatrix.sync.aligned.m8n8.x4.shared.b16 {%0,%1,%2,%3}, [%4];" \
                 : "=r"(r0), "=r"(r1), "=r"(r2), "=r"(r3) : "r"(addr))

#define MMA_F16(d, a, b0, b1) \
    asm volatile( \
        "mma.sync.aligned.m16n8k16.row.col.f32.f16.f16.f32 " \
        "{%0,%1,%2,%3},{%4,%5,%6,%7},{%8,%9},{%0,%1,%2,%3};" \
        : "+f"((d)[0]), "+f"((d)[1]), "+f"((d)[2]), "+f"((d)[3]) \
        : "r"((a)[0]), "r"((a)[1]), "r"((a)[2]), "r"((a)[3]), \
          "r"(b0), "r"(b1))

#define CP16(dst, src) \
    asm volatile("cp.async.cg.shared.global [%0], [%1], 16;" \
                 :: "r"(dst), "l"(src) : "memory")
#define CP_COMMIT() asm volatile("cp.async.commit_group;" ::: "memory")
#define CP_WAIT2()  asm volatile("cp.async.wait_group 2;" ::: "memory")

// 8 floats -> 8 fp16
__device__ __forceinline__ uint4 pack8(float4 v0, float4 v1) {
    float f[8] = {v0.x, v0.y, v0.z, v0.w, v1.x, v1.y, v1.z, v1.w};
    unsigned hw[4];
    #pragma unroll
    for (int i = 0; i < 4; ++i) {
        __half h0 = __float2half_rn(f[2 * i]);
        __half h1 = __float2half_rn(f[2 * i + 1]);
        hw[i] = ((unsigned)__half_as_ushort(h1) << 16) | __half_as_ushort(h0);
    }
    return make_uint4(hw[0], hw[1], hw[2], hw[3]);
}

// ---------------- split centroids (hi plane) + csq ----------------
__global__ void split_c_kernel(const float* __restrict__ C) {
    int row = blockIdx.x * 8 + (threadIdx.x >> 5);
    int lane = threadIdx.x & 31;
    const float4* p = (const float4*)(C + (size_t)row * D_DIM + lane * 8);
    float4 v0 = p[0], v1 = p[1];
    *(uint4*)(g_c_hi + (size_t)row * D_DIM + lane * 8) = pack8(v0, v1);
    float s = v0.x * v0.x + v0.y * v0.y + v0.z * v0.z + v0.w * v0.w
            + v1.x * v1.x + v1.y * v1.y + v1.z * v1.z + v1.w * v1.w;
    #pragma unroll
    for (int off = 16; off > 0; off >>= 1)
        s += __shfl_xor_sync(0xFFFFFFFFu, s, off);
    if (lane == 0) g_csq[row] = s;
}

// ---------------- split x (hi plane) ----------------
__global__ void split_x_kernel(const float* __restrict__ X) {
    int row = blockIdx.x * 8 + (threadIdx.x >> 5);
    int lane = threadIdx.x & 31;
    const float4* p = (const float4*)(X + (size_t)row * D_DIM + lane * 8);
    *(uint4*)(g_x_hi + (size_t)row * D_DIM + lane * 8) = pack8(p[0], p[1]);
}

// ---------------- Phase 1: 1-pass approx GEMM, A resident ----------------
__global__ void __launch_bounds__(THREADS, 1) gemm_approx_mma(int dummy) {
    extern __shared__ __align__(16) unsigned char smraw[];
    __shared__ unsigned long long sbest[BMT];

    const int tid = threadIdx.x;
    const int lane = tid & 31;
    const int wid = tid >> 5;
    const int wm = wid >> 2;        // 0..3 : m32 group
    const int wn = wid & 3;         // 0..3 : n32 group
    const int mt_idx = blockIdx.x & 31;
    const int ng = blockIdx.x >> 5;             // 0..31
    const int m0 = mt_idx * BMT;
    const int ntile0 = ng * NGT;

    if (tid < BMT) sbest[tid] = ~0ull;

    const uint32_t sbA = smem_u32(smraw);
    const uint32_t sbB = sbA + A_BYTES;

    const int lrow = tid >> 2;          // 0..127
    const int lseg0 = tid & 3;          // 16B seg

    // ---- A resident copy: 128 rows x 512B, 8 CP16 per thread ----
    {
        const __half* aSrc = g_x_hi + (size_t)(m0 + lrow) * D_DIM;
        const uint32_t dA = sbA + (uint32_t)(lrow * ROWA);
        #pragma unroll
        for (int s = 0; s < 8; ++s) {
            const int seg = lseg0 + s * 4;
            CP16(dA + seg * 16, aSrc + seg * 8);
        }
        CP_COMMIT();
    }

    // ---- B chunk issue (one CP16 per thread per chunk) ----
    #define ISSUE_B(cidx) do { \
        const int _j = (cidx) >> 3, _kc = (cidx) & 7; \
        const __half* _src = g_c_hi + \
            (size_t)((ntile0 + _j) * BNT + lrow) * D_DIM + _kc * KCH + lseg0 * 8; \
        const uint32_t _dst = sbB + \
            (uint32_t)(((cidx) & 3) * B_STAGE + lrow * ROWB + lseg0 * 16); \
        CP16(_dst, _src); \
        CP_COMMIT(); \
    } while (0)

    ISSUE_B(0); ISSUE_B(1); ISSUE_B(2);

    // ---- ldmatrix per-lane addresses (validated mapping) ----
    const uint32_t aRow = (uint32_t)((wm * 32 + (lane & 15)) * ROWA);
    const uint32_t aK   = (lane & 16) ? 16u : 0u;
    const uint32_t bRow = (uint32_t)((wn * 32 + (lane & 7) + ((lane & 16) >> 1)) * ROWB);
    const uint32_t bK   = (lane & 8) ? 16u : 0u;

    float acc[2][4][4];
    #pragma unroll
    for (int i = 0; i < 2; ++i)
        #pragma unroll
        for (int j = 0; j < 4; ++j)
            #pragma unroll
            for (int c = 0; c < 4; ++c) acc[i][j][c] = 0.0f;

    for (int cidx = 0; cidx < TOTCH; ++cidx) {
        CP_WAIT2();                 // chunk cidx (and A on iter 0) complete
        __syncthreads();            // visible to all; prev compute done
        if (cidx + 3 < TOTCH) ISSUE_B(cidx + 3);

        const int kc = cidx & 7;
        const uint32_t stgB = sbB + (uint32_t)((cidx & 3) * B_STAGE);
        #pragma unroll
        for (int ks = 0; ks < 2; ++ks) {
            const uint32_t kBB = (uint32_t)(ks * 32);
            const uint32_t kBA = (uint32_t)(kc * 64 + ks * 32);
            unsigned ah[2][4], bh[2][4];
            #pragma unroll
            for (int mt = 0; mt < 2; ++mt) {
                uint32_t a = sbA + aRow + (uint32_t)(mt * 16 * ROWA) + kBA + aK;
                LDSM4(ah[mt][0], ah[mt][1], ah[mt][2], ah[mt][3], a);
            }
            #pragma unroll
            for (int np = 0; np < 2; ++np) {
                uint32_t b = stgB + bRow + (uint32_t)(np * 16 * ROWB) + kBB + bK;
                LDSM4(bh[np][0], bh[np][1], bh[np][2], bh[np][3], b);
            }
            #pragma unroll
            for (int mt = 0; mt < 2; ++mt)
                #pragma unroll
                for (int nt = 0; nt < 4; ++nt) {
                    const int np = nt >> 1, r = (nt & 1) * 2;
                    MMA_F16(acc[mt][nt], ah[mt], bh[np][r], bh[np][r + 1]);
                }
        }

        if (kc == NCH - 1) {
            // ---- per-tile epilogue: approx dist + per-row CTA min ----
            const int ntile = ntile0 + (cidx >> 3);
            const int n0 = ntile * BNT;
            #pragma unroll
            for (int mt = 0; mt < 2; ++mt) {
                #pragma unroll
                for (int half = 0; half < 2; ++half) {
                    unsigned long long bk = ~0ull;
                    #pragma unroll
                    for (int nt = 0; nt < 4; ++nt) {
                        const int col = n0 + wn * 32 + nt * 8 + (lane & 3) * 2;
                        float2 cs = __ldg((const float2*)(g_csq + col));
                        float d0 = fmaf(-2.0f, acc[mt][nt][half * 2 + 0], cs.x);
                        float d1 = fmaf(-2.0f, acc[mt][nt][half * 2 + 1], cs.y);
                        unsigned long long k0 =
                            ((unsigned long long)enc_f32(d0) << 32) | (unsigned)col;
                        unsigned long long k1 =
                            ((unsigned long long)enc_f32(d1) << 32) | (unsigned)(col + 1);
                        unsigned long long km = k0 < k1 ? k0 : k1;
                        bk = km < bk ? km : bk;
                    }
                    unsigned long long o;
                    o = __shfl_xor_sync(0xFFFFFFFFu, bk, 1); bk = o < bk ? o : bk;
                    o = __shfl_xor_sync(0xFFFFFFFFu, bk, 2); bk = o < bk ? o : bk;
                    if ((lane & 3) == 0)
                        atomicMin(&sbest[wm * 32 + mt * 16 + half * 8 + (lane >> 2)], bk);
                }
            }
            __syncthreads();
            if (tid < BMT) {
                g_lmin[(size_t)(m0 + tid) * NT_TILES + ntile] = sbest[tid];
                sbest[tid] = ~0ull;
            }
            // reinit visible to all by the next loop-top __syncthreads
            #pragma unroll
            for (int i = 0; i < 2; ++i)
                #pragma unroll
                for (int j = 0; j < 4; ++j)
                    #pragma unroll
                    for (int c = 0; c < 4; ++c) acc[i][j][c] = 0.0f;
        }
    }
    #undef ISSUE_B
}

// ---------------- Phase 2: per-row exact rerank ----------------
__global__ void __launch_bounds__(128) rerank_kernel(
    const float* __restrict__ X, const float* __restrict__ Cc) {
    __shared__ __align__(16) float xs[D_DIM];
    __shared__ unsigned short cand[NT_TILES];
    __shared__ int ncand;
    __shared__ unsigned long long swarp[4];

    const int row = blockIdx.x;
    const int tid = threadIdx.x;
    const int lane = tid & 31;
    const int wid = tid >> 5;

    // parallel key load: 4 keys per thread
    const unsigned long long* lm = g_lmin + (size_t)row * NT_TILES;
    ulonglong2 ka = ((const ulonglong2*)lm)[tid * 2];
    ulonglong2 kb = ((const ulonglong2*)lm)[tid * 2 + 1];
    unsigned long long mn = ka.x < ka.y ? ka.x : ka.y;
    unsigned long long m2 = kb.x < kb.y ? kb.x : kb.y;
    mn = m2 < mn ? m2 : mn;

    xs[tid] = X[(size_t)row * D_DIM + tid];
    xs[tid + 128] = X[(size_t)row * D_DIM + 128 + tid];
    if (tid == 0) ncand = 0;

    #pragma unroll
    for (int off = 16; off > 0; off >>= 1) {
        unsigned long long o = __shfl_xor_sync(0xFFFFFFFFu, mn, off);
        mn = o < mn ? o : mn;
    }
    if (lane == 0) swarp[wid] = mn;
    __syncthreads();
    mn = swarp[0];
    #pragma unroll
    for (int w = 1; w < 4; ++w) mn = swarp[w] < mn ? swarp[w] : mn;

    const unsigned thr_enc = enc_f32(dec_f32((unsigned)(mn >> 32)) + M_MARGIN);

    if ((unsigned)(ka.x >> 32) <= thr_enc) cand[atomicAdd(&ncand, 1)] = tid * 4 + 0;
    if ((unsigned)(ka.y >> 32) <= thr_enc) cand[atomicAdd(&ncand, 1)] = tid * 4 + 1;
    if ((unsigned)(kb.x >> 32) <= thr_enc) cand[atomicAdd(&ncand, 1)] = tid * 4 + 2;
    if ((unsigned)(kb.y >> 32) <= thr_enc) cand[atomicAdd(&ncand, 1)] = tid * 4 + 3;
    __syncthreads();
    const int nc = ncand;

    // each thread owns one column per candidate tile; exact fp32 dot
    unsigned long long best = ~0ull;
    const float4* xp = (const float4*)xs;
    for (int i = 0; i < nc; ++i) {
        const int col = (int)cand[i] * BNT + tid;
        const float4* cp = (const float4*)(Cc + (size_t)col * D_DIM);
        float s0 = 0.f, s1 = 0.f, s2 = 0.f, s3 = 0.f;
        #pragma unroll
        for (int q = 0; q < 64; q += 4) {
            float4 v0 = cp[q], v1 = cp[q + 1], v2 = cp[q + 2], v3 = cp[q + 3];
            float4 u0 = xp[q], u1 = xp[q + 1], u2 = xp[q + 2], u3 = xp[q + 3];
            s0 = fmaf(v0.x, u0.x, s0); s0 = fmaf(v0.y, u0.y, s0);
            s0 = fmaf(v0.z, u0.z, s0); s0 = fmaf(v0.w, u0.w, s0);
            s1 = fmaf(v1.x, u1.x, s1); s1 = fmaf(v1.y, u1.y, s1);
            s1 = fmaf(v1.z, u1.z, s1); s1 = fmaf(v1.w, u1.w, s1);
            s2 = fmaf(v2.x, u2.x, s2); s2 = fmaf(v2.y, u2.y, s2);
            s2 = fmaf(v2.z, u2.z, s2); s2 = fmaf(v2.w, u2.w, s2);
            s3 = fmaf(v3.x, u3.x, s3); s3 = fmaf(v3.y, u3.y, s3);
            s3 = fmaf(v3.z, u3.z, s3); s3 = fmaf(v3.w, u3.w, s3);
        }
        float s = (s0 + s1) + (s2 + s3);
        float dist = fmaf(-2.0f, s, __ldg(&g_csq[col]));
        unsigned long long key =
            ((unsigned long long)enc_f32(dist) << 32) | (unsigned)col;
        best = key < best ? key : best;
    }

    // block-reduce best
    #pragma unroll
    for (int off = 16; off > 0; off >>= 1) {
        unsigned long long o = __shfl_xor_sync(0xFFFFFFFFu, best, off);
        best = o < best ? o : best;
    }
    __syncthreads();
    if (lane == 0) swarp[wid] = best;
    __syncthreads();
    if (tid == 0) {
        unsigned long long b = swarp[0];
        #pragma unroll
        for (int w = 1; w < 4; ++w) b = swarp[w] < b ? swarp[w] : b;
        g_best[row] = b;
    }
}

// ---------------- gather winners + codes ----------------
__global__ void gather_kernel(const float* __restrict__ C, float* __restrict__ out,
                              int B) {
    int b = blockIdx.x;
    unsigned long long key = g_best[b];
    unsigned idx = (unsigned)(key & 0xFFFFFFFFull);
    const float* src = C + (size_t)idx * D_DIM;
    out[(size_t)b * D_DIM + threadIdx.x] = src[threadIdx.x];
    if (threadIdx.x == 0)
        out[(size_t)B * D_DIM + b] = (float)idx;
}

extern "C" void kernel_launch(void* const* d_in, const int* in_sizes, int n_in,
                              void* d_out, int out_size) {
    const float* x = (const float*)d_in[1];
    const float* cent = (const float*)d_in[2];
    const int B = in_sizes[1] / D_DIM;      // 4096
    const int K = in_sizes[2] / D_DIM;      // 65536
    float* out = (float*)d_out;

    static int smem_set = 0;
    if (!smem_set) {
        cudaFuncSetAttribute(gemm_approx_mma,
                             cudaFuncAttributeMaxDynamicSharedMemorySize, SMEM_DYN);
        smem_set = 1;
    }

    split_c_kernel<<<K / 8, 256>>>(cent);
    split_x_kernel<<<B / 8, 256>>>(x);
    const int grid = 32 * 32;                // m-tiles x n-groups = 1024
    gemm_approx_mma<<<grid, THREADS, SMEM_DYN>>>(0);
    rerank_kernel<<<B, 128>>>(x, cent);
    gather_kernel<<<B, D_DIM>>>(cent, out, B);
}

// round 10
// speedup vs baseline: 3.9964x; 1.1354x over previous
#include <cuda_runtime.h>
#include <cuda_fp16.h>
#include <cstdint>

// ============================================================
// IVFBook: dist = ||c||^2 - 2 x.c ; codes = argmin ; out = C[codes]
// B=4096, D=256, K=65536.
// Phase 1: 1-pass fp16 mma.sync approx GEMM (A-resident smem,
//          B-only 4-stage cp.async pipeline, KCH=64), per-(row,tile)
//          encoded min-distance (u32).
// Phase 2: per-row exact fp32 rerank of tiles within margin of the
//          global approx min (provably safe bound), coalesced.
// Output float32: [B*D quantized x][B codes-as-float]
// ============================================================

#define D_DIM 256
#define BMT 128          // CTA M tile
#define BNT 128          // N tile
#define KCH 64           // K chunk (fp16 elems) = 128B row
#define NCHT 4           // chunks per n-tile (D_DIM/KCH)
#define THREADS 512
#define ROWB 144         // B smem row stride (bytes): 36 words == 4 mod 32
#define ROWA 528         // A smem row stride (bytes)
#define NT_TILES 512     // K / BNT
#define NGT 16           // n-tiles per CTA
#define TOTCH (NGT * NCHT)  // 64 chunks per CTA
#define M_MARGIN 0.75f

#define A_BYTES (128 * ROWA)      // 67584
#define B_STAGE (128 * ROWB)      // 18432
#define NSTAGE 4
#define SMEM_DYN (A_BYTES + NSTAGE * B_STAGE)   // 141312

__device__ unsigned long long g_best[4096];
__device__ unsigned g_lmin[4096 * NT_TILES];   // 8MB, encoded f32 dists
__device__ float g_csq[65536];
__device__ __half g_c_hi[65536 * 256];
__device__ __half g_x_hi[4096 * 256];

__device__ __forceinline__ unsigned enc_f32(float f) {
    unsigned u = __float_as_uint(f);
    return (u & 0x80000000u) ? ~u : (u | 0x80000000u);
}
__device__ __forceinline__ float dec_f32(unsigned u) {
    unsigned v = (u & 0x80000000u) ? (u & 0x7FFFFFFFu) : ~u;
    return __uint_as_float(v);
}
__device__ __forceinline__ uint32_t smem_u32(const void* p) {
    uint32_t a;
    asm("{ .reg .u64 t; cvta.to.shared.u64 t, %1; cvt.u32.u64 %0, t; }"
        : "=r"(a) : "l"(p));
    return a;
}

#define LDSM4(r0, r1, r2, r3, addr) \
    asm volatile("ldmatrix.sync.aligned.m8n8.x4.shared.b16 {%0,%1,%2,%3}, [%4];" \
                 : "=r"(r0), "=r"(r1), "=r"(r2), "=r"(r3) : "r"(addr))

#define MMA_F16(d, a, b0, b1) \
    asm volatile( \
        "mma.sync.aligned.m16n8k16.row.col.f32.f16.f16.f32 " \
        "{%0,%1,%2,%3},{%4,%5,%6,%7},{%8,%9},{%0,%1,%2,%3};" \
        : "+f"((d)[0]), "+f"((d)[1]), "+f"((d)[2]), "+f"((d)[3]) \
        : "r"((a)[0]), "r"((a)[1]), "r"((a)[2]), "r"((a)[3]), \
          "r"(b0), "r"(b1))

#define CP16(dst, src) \
    asm volatile("cp.async.cg.shared.global [%0], [%1], 16;" \
                 :: "r"(dst), "l"(src) : "memory")
#define CP_COMMIT() asm volatile("cp.async.commit_group;" ::: "memory")
#define CP_WAIT2()  asm volatile("cp.async.wait_group 2;" ::: "memory")

// 8 floats -> 8 fp16
__device__ __forceinline__ uint4 pack8(float4 v0, float4 v1) {
    float f[8] = {v0.x, v0.y, v0.z, v0.w, v1.x, v1.y, v1.z, v1.w};
    unsigned hw[4];
    #pragma unroll
    for (int i = 0; i < 4; ++i) {
        __half h0 = __float2half_rn(f[2 * i]);
        __half h1 = __float2half_rn(f[2 * i + 1]);
        hw[i] = ((unsigned)__half_as_ushort(h1) << 16) | __half_as_ushort(h0);
    }
    return make_uint4(hw[0], hw[1], hw[2], hw[3]);
}

// ---------------- split centroids (hi plane) + csq ----------------
__global__ void split_c_kernel(const float* __restrict__ C) {
    int row = blockIdx.x * 8 + (threadIdx.x >> 5);
    int lane = threadIdx.x & 31;
    const float4* p = (const float4*)(C + (size_t)row * D_DIM + lane * 8);
    float4 v0 = p[0], v1 = p[1];
    *(uint4*)(g_c_hi + (size_t)row * D_DIM + lane * 8) = pack8(v0, v1);
    float s = v0.x * v0.x + v0.y * v0.y + v0.z * v0.z + v0.w * v0.w
            + v1.x * v1.x + v1.y * v1.y + v1.z * v1.z + v1.w * v1.w;
    #pragma unroll
    for (int off = 16; off > 0; off >>= 1)
        s += __shfl_xor_sync(0xFFFFFFFFu, s, off);
    if (lane == 0) g_csq[row] = s;
}

// ---------------- split x (hi plane) ----------------
__global__ void split_x_kernel(const float* __restrict__ X) {
    int row = blockIdx.x * 8 + (threadIdx.x >> 5);
    int lane = threadIdx.x & 31;
    const float4* p = (const float4*)(X + (size_t)row * D_DIM + lane * 8);
    *(uint4*)(g_x_hi + (size_t)row * D_DIM + lane * 8) = pack8(p[0], p[1]);
}

// ---------------- Phase 1: 1-pass approx GEMM, A resident ----------------
__global__ void __launch_bounds__(THREADS, 1) gemm_approx_mma(int dummy) {
    extern __shared__ __align__(16) unsigned char smraw[];
    __shared__ unsigned long long sbest[BMT];

    const int tid = threadIdx.x;
    const int lane = tid & 31;
    const int wid = tid >> 5;
    const int wm = wid >> 2;        // 0..3 : m32 group
    const int wn = wid & 3;         // 0..3 : n32 group
    const int mt_idx = blockIdx.x & 31;
    const int ng = blockIdx.x >> 5;             // 0..31
    const int m0 = mt_idx * BMT;
    const int ntile0 = ng * NGT;

    if (tid < BMT) sbest[tid] = ~0ull;

    const uint32_t sbA = smem_u32(smraw);
    const uint32_t sbB = sbA + A_BYTES;

    const int lrow = tid >> 2;          // 0..127
    const int lseg0 = tid & 3;          // 16B seg

    // ---- A resident copy: 128 rows x 512B, 8 CP16 per thread ----
    {
        const __half* aSrc = g_x_hi + (size_t)(m0 + lrow) * D_DIM;
        const uint32_t dA = sbA + (uint32_t)(lrow * ROWA);
        #pragma unroll
        for (int s = 0; s < 8; ++s) {
            const int seg = lseg0 + s * 4;
            CP16(dA + seg * 16, aSrc + seg * 8);
        }
        CP_COMMIT();
    }

    // ---- B chunk issue (two CP16 per thread: 128B per row) ----
    #define ISSUE_B(cidx) do { \
        const int _j = (cidx) >> 2, _kc = (cidx) & 3; \
        const __half* _src = g_c_hi + \
            (size_t)((ntile0 + _j) * BNT + lrow) * D_DIM + _kc * KCH + lseg0 * 8; \
        const uint32_t _dst = sbB + \
            (uint32_t)(((cidx) & 3) * B_STAGE + lrow * ROWB + lseg0 * 16); \
        CP16(_dst, _src); \
        CP16(_dst + 64, _src + 32); \
        CP_COMMIT(); \
    } while (0)

    ISSUE_B(0); ISSUE_B(1); ISSUE_B(2);

    // ---- ldmatrix per-lane addresses (validated mapping; new strides) ----
    const uint32_t aRow = (uint32_t)((wm * 32 + (lane & 15)) * ROWA);
    const uint32_t aK   = (lane & 16) ? 16u : 0u;
    const uint32_t bRow = (uint32_t)((wn * 32 + (lane & 7) + ((lane & 16) >> 1)) * ROWB);
    const uint32_t bK   = (lane & 8) ? 16u : 0u;

    float acc[2][4][4];
    #pragma unroll
    for (int i = 0; i < 2; ++i)
        #pragma unroll
        for (int j = 0; j < 4; ++j)
            #pragma unroll
            for (int c = 0; c < 4; ++c) acc[i][j][c] = 0.0f;

    for (int cidx = 0; cidx < TOTCH; ++cidx) {
        CP_WAIT2();                 // chunk cidx (and A on iter 0) complete
        __syncthreads();
        if (cidx + 3 < TOTCH) ISSUE_B(cidx + 3);

        const int kc = cidx & 3;
        const uint32_t stgB = sbB + (uint32_t)((cidx & 3) * B_STAGE);
        #pragma unroll
        for (int ks = 0; ks < 4; ++ks) {         // four k16 steps per chunk
            const uint32_t kBB = (uint32_t)(ks * 32);
            const uint32_t kBA = (uint32_t)(kc * 128 + ks * 32);
            unsigned ah[2][4], bh[2][4];
            #pragma unroll
            for (int mt = 0; mt < 2; ++mt) {
                uint32_t a = sbA + aRow + (uint32_t)(mt * 16 * ROWA) + kBA + aK;
                LDSM4(ah[mt][0], ah[mt][1], ah[mt][2], ah[mt][3], a);
            }
            #pragma unroll
            for (int np = 0; np < 2; ++np) {
                uint32_t b = stgB + bRow + (uint32_t)(np * 16 * ROWB) + kBB + bK;
                LDSM4(bh[np][0], bh[np][1], bh[np][2], bh[np][3], b);
            }
            #pragma unroll
            for (int mt = 0; mt < 2; ++mt)
                #pragma unroll
                for (int nt = 0; nt < 4; ++nt) {
                    const int np = nt >> 1, r = (nt & 1) * 2;
                    MMA_F16(acc[mt][nt], ah[mt], bh[np][r], bh[np][r + 1]);
                }
        }

        if (kc == NCHT - 1) {
            // ---- per-tile epilogue: approx dist + per-row CTA min ----
            const int ntile = ntile0 + (cidx >> 2);
            const int n0 = ntile * BNT;
            #pragma unroll
            for (int mt = 0; mt < 2; ++mt) {
                #pragma unroll
                for (int half = 0; half < 2; ++half) {
                    unsigned long long bk = ~0ull;
                    #pragma unroll
                    for (int nt = 0; nt < 4; ++nt) {
                        const int col = n0 + wn * 32 + nt * 8 + (lane & 3) * 2;
                        float2 cs = __ldg((const float2*)(g_csq + col));
                        float d0 = fmaf(-2.0f, acc[mt][nt][half * 2 + 0], cs.x);
                        float d1 = fmaf(-2.0f, acc[mt][nt][half * 2 + 1], cs.y);
                        unsigned long long k0 =
                            ((unsigned long long)enc_f32(d0) << 32) | (unsigned)col;
                        unsigned long long k1 =
                            ((unsigned long long)enc_f32(d1) << 32) | (unsigned)(col + 1);
                        unsigned long long km = k0 < k1 ? k0 : k1;
                        bk = km < bk ? km : bk;
                    }
                    unsigned long long o;
                    o = __shfl_xor_sync(0xFFFFFFFFu, bk, 1); bk = o < bk ? o : bk;
                    o = __shfl_xor_sync(0xFFFFFFFFu, bk, 2); bk = o < bk ? o : bk;
                    if ((lane & 3) == 0)
                        atomicMin(&sbest[wm * 32 + mt * 16 + half * 8 + (lane >> 2)], bk);
                }
            }
            __syncthreads();
            if (tid < BMT) {
                g_lmin[(size_t)(m0 + tid) * NT_TILES + ntile] =
                    (unsigned)(sbest[tid] >> 32);
                sbest[tid] = ~0ull;
            }
            #pragma unroll
            for (int i = 0; i < 2; ++i)
                #pragma unroll
                for (int j = 0; j < 4; ++j)
                    #pragma unroll
                    for (int c = 0; c < 4; ++c) acc[i][j][c] = 0.0f;
        }
    }
    #undef ISSUE_B
}

// ---------------- Phase 2: per-row exact rerank (coalesced) ----------------
__global__ void __launch_bounds__(128) rerank_kernel(
    const float* __restrict__ X, const float* __restrict__ Cc) {
    __shared__ __align__(16) float xs[D_DIM];
    __shared__ unsigned short cand[NT_TILES];
    __shared__ int ncand;
    __shared__ unsigned suw[4];
    __shared__ unsigned long long swarp[4];

    const int row = blockIdx.x;
    const int tid = threadIdx.x;
    const int lane = tid & 31;
    const int wid = tid >> 5;
    const int cg = lane >> 3;       // column group within warp (0..3)
    const int sl = lane & 7;        // sub-lane within group

    // parallel key load: 4 encoded u32 per thread
    const unsigned* lm = g_lmin + (size_t)row * NT_TILES;
    uint4 k4 = ((const uint4*)lm)[tid];
    unsigned mn = k4.x < k4.y ? k4.x : k4.y;
    unsigned m2 = k4.z < k4.w ? k4.z : k4.w;
    mn = m2 < mn ? m2 : mn;

    xs[tid] = X[(size_t)row * D_DIM + tid];
    xs[tid + 128] = X[(size_t)row * D_DIM + 128 + tid];   // FIX: full 256-dim row
    if (tid == 0) ncand = 0;

    #pragma unroll
    for (int off = 16; off > 0; off >>= 1) {
        unsigned o = __shfl_xor_sync(0xFFFFFFFFu, mn, off);
        mn = o < mn ? o : mn;
    }
    if (lane == 0) suw[wid] = mn;
    __syncthreads();
    mn = suw[0];
    #pragma unroll
    for (int w = 1; w < 4; ++w) mn = suw[w] < mn ? suw[w] : mn;

    const unsigned thr_enc = enc_f32(dec_f32(mn) + M_MARGIN);

    if (k4.x <= thr_enc) cand[atomicAdd(&ncand, 1)] = tid * 4 + 0;
    if (k4.y <= thr_enc) cand[atomicAdd(&ncand, 1)] = tid * 4 + 1;
    if (k4.z <= thr_enc) cand[atomicAdd(&ncand, 1)] = tid * 4 + 2;
    if (k4.w <= thr_enc) cand[atomicAdd(&ncand, 1)] = tid * 4 + 3;
    __syncthreads();
    const int nc = ncand;

    // coalesced exact fp32: 4 cols per warp per pass (8 lanes per col)
    unsigned long long best = ~0ull;
    const float4* xp = (const float4*)xs;
    for (int i = 0; i < nc; ++i) {
        const int tbase = (int)cand[i] * BNT;
        #pragma unroll
        for (int p = 0; p < 8; ++p) {
            const int col = tbase + p * 16 + wid * 4 + cg;
            const float4* cp = (const float4*)(Cc + (size_t)col * D_DIM);
            float s = 0.f;
            #pragma unroll
            for (int j = 0; j < 8; ++j) {
                float4 v = cp[sl + j * 8];
                float4 u = xp[sl + j * 8];
                s = fmaf(v.x, u.x, s); s = fmaf(v.y, u.y, s);
                s = fmaf(v.z, u.z, s); s = fmaf(v.w, u.w, s);
            }
            s += __shfl_xor_sync(0xFFFFFFFFu, s, 1);
            s += __shfl_xor_sync(0xFFFFFFFFu, s, 2);
            s += __shfl_xor_sync(0xFFFFFFFFu, s, 4);
            if (sl == 0) {
                float dist = fmaf(-2.0f, s, __ldg(&g_csq[col]));
                unsigned long long key =
                    ((unsigned long long)enc_f32(dist) << 32) | (unsigned)col;
                best = key < best ? key : best;
            }
        }
    }

    // block-reduce best
    #pragma unroll
    for (int off = 16; off > 0; off >>= 1) {
        unsigned long long o = __shfl_xor_sync(0xFFFFFFFFu, best, off);
        best = o < best ? o : best;
    }
    if (lane == 0) swarp[wid] = best;
    __syncthreads();
    if (tid == 0) {
        unsigned long long b = swarp[0];
        #pragma unroll
        for (int w = 1; w < 4; ++w) b = swarp[w] < b ? swarp[w] : b;
        g_best[row] = b;
    }
}

// ---------------- gather winners + codes ----------------
__global__ void gather_kernel(const float* __restrict__ C, float* __restrict__ out,
                              int B) {
    int b = blockIdx.x;
    unsigned long long key = g_best[b];
    unsigned idx = (unsigned)(key & 0xFFFFFFFFull);
    const float* src = C + (size_t)idx * D_DIM;
    out[(size_t)b * D_DIM + threadIdx.x] = src[threadIdx.x];
    if (threadIdx.x == 0)
        out[(size_t)B * D_DIM + b] = (float)idx;
}

extern "C" void kernel_launch(void* const* d_in, const int* in_sizes, int n_in,
                              void* d_out, int out_size) {
    const float* x = (const float*)d_in[1];
    const float* cent = (const float*)d_in[2];
    const int B = in_sizes[1] / D_DIM;      // 4096
    const int K = in_sizes[2] / D_DIM;      // 65536
    float* out = (float*)d_out;

    static int smem_set = 0;
    if (!smem_set) {
        cudaFuncSetAttribute(gemm_approx_mma,
                             cudaFuncAttributeMaxDynamicSharedMemorySize, SMEM_DYN);
        smem_set = 1;
    }

    split_c_kernel<<<K / 8, 256>>>(cent);
    split_x_kernel<<<B / 8, 256>>>(x);
    const int grid = 32 * 32;                // m-tiles x n-groups = 1024
    gemm_approx_mma<<<grid, THREADS, SMEM_DYN>>>(0);
    rerank_kernel<<<B, 128>>>(x, cent);
    gather_kernel<<<B, D_DIM>>>(cent, out, B);
}